// round 3
// baseline (speedup 1.0000x reference)
#include <cuda_runtime.h>
#include <cstdint>

#define N_   128
#define C_   128
#define H_   56
#define W_   56
#define O_   32
#define KW_  3

#define ROWS    8     // output h rows per block
#define C_CH    64    // channels staged per chunk
#define THREADS 224   // 8 rows * 28 units (7 w-groups * 4 o-groups)

#define SW_ELEMS   (C_ * KW_ * O_)          // 12288 floats, layout [c][k][o]
#define SX_STRIDE_R 58                      // 56 data + 2 zero pads (w=-1, w=56)
#define SX_STRIDE_C (ROWS * SX_STRIDE_R)    // 464
#define SX_ELEMS   (C_CH * SX_STRIDE_C)     // 29696 floats
#define SMEM_BYTES ((SW_ELEMS + SX_ELEMS) * 4)  // 167936 B

extern __shared__ float smem_f[];

typedef unsigned long long ull;

__device__ __forceinline__ ull fma2(ull a, ull b, ull c) {
    ull d;
    asm("fma.rn.f32x2 %0, %1, %2, %3;" : "=l"(d) : "l"(a), "l"(b), "l"(c));
    return d;
}

__device__ __forceinline__ ull pack2(float x) {
    ull d;
    unsigned int u = __float_as_uint(x);
    asm("mov.b64 %0, {%1, %1};" : "=l"(d) : "r"(u));
    return d;
}

__device__ __forceinline__ float lo32(ull v) { return __uint_as_float((unsigned int)v); }
__device__ __forceinline__ float hi32(ull v) { return __uint_as_float((unsigned int)(v >> 32)); }

__global__ void __launch_bounds__(THREADS, 1)
conv1x3_roll_kernel(const float* __restrict__ x,
                    const float* __restrict__ wgt,
                    float* __restrict__ out) {
    float* sw = smem_f;             // [c][k][o] : 128*3*32
    float* sx = smem_f + SW_ELEMS;  // [c][r][58], value for width ww at index ww+1

    const int n      = blockIdx.x;
    const int h_base = blockIdx.y * ROWS;
    const int tid    = threadIdx.x;

    const int r   = tid / 28;       // 0..7 output row within tile
    const int u   = tid % 28;
    const int w_g = u >> 2;         // 0..6  -> w0 = 8*w_g
    const int o_g = u & 3;          // 0..3  -> o0 = 8*o_g
    const int w0  = w_g * 8;
    const int o0  = o_g * 8;
    const int h   = h_base + r;     // output h this thread produces

    // ---- stage all weights once: sw[c][k][o] = wgt[o][c][k] ----
    for (int idx = tid; idx < SW_ELEMS; idx += THREADS) {
        int o = idx & 31;
        int k = (idx >> 5) % 3;
        int c = idx / 96;
        sw[idx] = wgt[(o * C_ + c) * KW_ + k];
    }

    ull acc[4][8];
#pragma unroll
    for (int p = 0; p < 4; ++p)
#pragma unroll
        for (int i = 0; i < 8; ++i) acc[p][i] = 0ull;

    for (int cc = 0; cc < C_ / C_CH; ++cc) {
        const int c0 = cc * C_CH;
        if (cc) __syncthreads();   // previous compute done before overwriting sx

        // ---- stage x chunk: rows hsrc = (h_base + rr - 1) mod 56, widths 0..55 ----
        for (int q = tid; q < C_CH * ROWS * 14; q += THREADS) {
            int v  = q % 14;              // float4 index within row
            int rr = (q / 14) % ROWS;
            int c  = q / (14 * ROWS);
            int hs = h_base + rr - 1;
            if (hs < 0) hs += H_;
            const float4 val = *reinterpret_cast<const float4*>(
                x + (((size_t)n * C_ + (c0 + c)) * H_ + hs) * W_ + v * 4);
            float* dst = sx + c * SX_STRIDE_C + rr * SX_STRIDE_R + 1 + v * 4;
            dst[0] = val.x; dst[1] = val.y; dst[2] = val.z; dst[3] = val.w;
        }
        // zero pads at w=-1 and w=56
        for (int q = tid; q < C_CH * ROWS; q += THREADS) {
            int rr = q % ROWS;
            int c  = q / ROWS;
            float* row = sx + c * SX_STRIDE_C + rr * SX_STRIDE_R;
            row[0]  = 0.0f;
            row[57] = 0.0f;
        }
        __syncthreads();

        // ---- accumulate over this chunk ----
        for (int c = 0; c < C_CH; ++c) {
            const float* xrow = sx + c * SX_STRIDE_C + r * SX_STRIDE_R + w0;
            ull xd[10];
#pragma unroll
            for (int j = 0; j < 10; ++j) xd[j] = pack2(xrow[j]);

            const float* wrow = sw + (c0 + c) * (KW_ * O_) + o0;
#pragma unroll
            for (int k = 0; k < 3; ++k) {
#pragma unroll
                for (int p = 0; p < 4; ++p) {
                    ull wp = *reinterpret_cast<const ull*>(wrow + k * O_ + 2 * p);
#pragma unroll
                    for (int i = 0; i < 8; ++i)
                        acc[p][i] = fma2(xd[i + k], wp, acc[p][i]);
                }
            }
        }
    }

    // ---- write out: acc[p][i] holds (o=o0+2p, o=o0+2p+1) at w = w0+i ----
#pragma unroll
    for (int p = 0; p < 4; ++p) {
        float* dst_lo = out + (((size_t)n * O_ + (o0 + 2 * p)) * H_ + h) * W_ + w0;
        float* dst_hi = dst_lo + (size_t)H_ * W_;
        float4 a, b;
        a.x = lo32(acc[p][0]); a.y = lo32(acc[p][1]); a.z = lo32(acc[p][2]); a.w = lo32(acc[p][3]);
        b.x = lo32(acc[p][4]); b.y = lo32(acc[p][5]); b.z = lo32(acc[p][6]); b.w = lo32(acc[p][7]);
        *reinterpret_cast<float4*>(dst_lo)     = a;
        *reinterpret_cast<float4*>(dst_lo + 4) = b;
        a.x = hi32(acc[p][0]); a.y = hi32(acc[p][1]); a.z = hi32(acc[p][2]); a.w = hi32(acc[p][3]);
        b.x = hi32(acc[p][4]); b.y = hi32(acc[p][5]); b.z = hi32(acc[p][6]); b.w = hi32(acc[p][7]);
        *reinterpret_cast<float4*>(dst_hi)     = a;
        *reinterpret_cast<float4*>(dst_hi + 4) = b;
    }
}

extern "C" void kernel_launch(void* const* d_in, const int* in_sizes, int n_in,
                              void* d_out, int out_size) {
    const float* x = (const float*)d_in[0];
    const float* w = (const float*)d_in[1];
    // safety: identify inputs by size in case of ordering surprises
    if (n_in >= 2 && in_sizes[0] == O_ * C_ * KW_) {
        const float* t = x; x = w; w = t;
    }
    float* out = (float*)d_out;

    cudaFuncSetAttribute(conv1x3_roll_kernel,
                         cudaFuncAttributeMaxDynamicSharedMemorySize, SMEM_BYTES);

    dim3 grid(N_, H_ / ROWS);  // 128 x 7
    conv1x3_roll_kernel<<<grid, THREADS, SMEM_BYTES>>>(x, w, out);
}

// round 4
// speedup vs baseline: 1.6581x; 1.6581x over previous
#include <cuda_runtime.h>
#include <cstdint>

#define N_   128
#define C_   128
#define H_   56
#define W_   56
#define O_   32
#define KW_  3

#define ROWS    8     // output h rows per block
#define C_CH    64    // channels staged per chunk
#define THREADS 448   // 8 rows * 56 units (7 w-groups * 8 o-groups)

#define SW_ELEMS   (C_ * KW_ * O_)          // 12288 floats, layout [c][k][o]
#define SX_STRIDE_R 58                      // 56 data + 2 zero pads (w=-1, w=56)
#define SX_STRIDE_C (ROWS * SX_STRIDE_R)    // 464
#define SX_ELEMS   (C_CH * SX_STRIDE_C)     // 29696 floats
#define SMEM_BYTES ((SW_ELEMS + SX_ELEMS) * 4)  // 167936 B

extern __shared__ float smem_f[];

typedef unsigned long long ull;

__device__ __forceinline__ ull fma2(ull a, ull b, ull c) {
    ull d;
    asm("fma.rn.f32x2 %0, %1, %2, %3;" : "=l"(d) : "l"(a), "l"(b), "l"(c));
    return d;
}

__device__ __forceinline__ ull pack2(float x) {
    ull d;
    unsigned int u = __float_as_uint(x);
    asm("mov.b64 %0, {%1, %1};" : "=l"(d) : "r"(u));
    return d;
}

__device__ __forceinline__ float lo32(ull v) { return __uint_as_float((unsigned int)v); }
__device__ __forceinline__ float hi32(ull v) { return __uint_as_float((unsigned int)(v >> 32)); }

__global__ void __launch_bounds__(THREADS, 1)
conv1x3_roll_kernel(const float* __restrict__ x,
                    const float* __restrict__ wgt,
                    float* __restrict__ out) {
    float* sw = smem_f;             // [c][k][o] : 128*3*32
    float* sx = smem_f + SW_ELEMS;  // [c][r][58], value for width ww at index ww+1

    const int n      = blockIdx.x;
    const int h_base = blockIdx.y * ROWS;
    const int tid    = threadIdx.x;

    const int r   = tid / 56;       // 0..7 output row within tile
    const int u   = tid % 56;
    const int w_g = u >> 3;         // 0..6  -> w0 = 8*w_g
    const int o_g = u & 7;          // 0..7  -> o0 = 4*o_g
    const int w0  = w_g * 8;
    const int o0  = o_g * 4;
    const int h   = h_base + r;     // output h this thread produces

    // ---- stage all weights once: sw[c][k][o] = wgt[o][c][k] ----
    for (int idx = tid; idx < SW_ELEMS; idx += THREADS) {
        int o = idx & 31;
        int k = (idx >> 5) % 3;
        int c = idx / 96;
        sw[idx] = wgt[(o * C_ + c) * KW_ + k];
    }

    ull acc[2][8];   // [o-pair p][w-offset i]; p covers o = o0+2p, o0+2p+1
#pragma unroll
    for (int p = 0; p < 2; ++p)
#pragma unroll
        for (int i = 0; i < 8; ++i) acc[p][i] = 0ull;

    for (int cc = 0; cc < C_ / C_CH; ++cc) {
        const int c0 = cc * C_CH;
        if (cc) __syncthreads();   // previous compute done before overwriting sx

        // ---- stage x chunk: rows hsrc = (h_base + rr - 1) mod 56, widths 0..55 ----
        for (int q = tid; q < C_CH * ROWS * 14; q += THREADS) {
            int v  = q % 14;              // float4 index within row
            int rr = (q / 14) % ROWS;
            int c  = q / (14 * ROWS);
            int hs = h_base + rr - 1;
            if (hs < 0) hs += H_;
            const float4 val = *reinterpret_cast<const float4*>(
                x + (((size_t)n * C_ + (c0 + c)) * H_ + hs) * W_ + v * 4);
            float* dst = sx + c * SX_STRIDE_C + rr * SX_STRIDE_R + 1 + v * 4;
            dst[0] = val.x; dst[1] = val.y; dst[2] = val.z; dst[3] = val.w;
        }
        // zero pads at w=-1 and w=56
        for (int q = tid; q < C_CH * ROWS; q += THREADS) {
            int rr = q % ROWS;
            int c  = q / ROWS;
            float* row = sx + c * SX_STRIDE_C + rr * SX_STRIDE_R;
            row[0]  = 0.0f;
            row[57] = 0.0f;
        }
        __syncthreads();

        // ---- accumulate over this chunk ----
        for (int c = 0; c < C_CH; ++c) {
            const float* xrow = sx + c * SX_STRIDE_C + r * SX_STRIDE_R + w0;
            ull xd[10];
#pragma unroll
            for (int j = 0; j < 10; ++j) xd[j] = pack2(xrow[j]);

            const float* wrow = sw + (c0 + c) * (KW_ * O_) + o0;
#pragma unroll
            for (int k = 0; k < 3; ++k) {
#pragma unroll
                for (int p = 0; p < 2; ++p) {
                    ull wp = *reinterpret_cast<const ull*>(wrow + k * O_ + 2 * p);
#pragma unroll
                    for (int i = 0; i < 8; ++i)
                        acc[p][i] = fma2(xd[i + k], wp, acc[p][i]);
                }
            }
        }
    }

    // ---- write out: acc[p][i] holds (o=o0+2p, o=o0+2p+1) at w = w0+i ----
#pragma unroll
    for (int p = 0; p < 2; ++p) {
        float* dst_lo = out + (((size_t)n * O_ + (o0 + 2 * p)) * H_ + h) * W_ + w0;
        float* dst_hi = dst_lo + (size_t)H_ * W_;
        float4 a, b;
        a.x = lo32(acc[p][0]); a.y = lo32(acc[p][1]); a.z = lo32(acc[p][2]); a.w = lo32(acc[p][3]);
        b.x = lo32(acc[p][4]); b.y = lo32(acc[p][5]); b.z = lo32(acc[p][6]); b.w = lo32(acc[p][7]);
        *reinterpret_cast<float4*>(dst_lo)     = a;
        *reinterpret_cast<float4*>(dst_lo + 4) = b;
        a.x = hi32(acc[p][0]); a.y = hi32(acc[p][1]); a.z = hi32(acc[p][2]); a.w = hi32(acc[p][3]);
        b.x = hi32(acc[p][4]); b.y = hi32(acc[p][5]); b.z = hi32(acc[p][6]); b.w = hi32(acc[p][7]);
        *reinterpret_cast<float4*>(dst_hi)     = a;
        *reinterpret_cast<float4*>(dst_hi + 4) = b;
    }
}

extern "C" void kernel_launch(void* const* d_in, const int* in_sizes, int n_in,
                              void* d_out, int out_size) {
    const float* x = (const float*)d_in[0];
    const float* w = (const float*)d_in[1];
    // safety: identify inputs by size in case of ordering surprises
    if (n_in >= 2 && in_sizes[0] == O_ * C_ * KW_) {
        const float* t = x; x = w; w = t;
    }
    float* out = (float*)d_out;

    cudaFuncSetAttribute(conv1x3_roll_kernel,
                         cudaFuncAttributeMaxDynamicSharedMemorySize, SMEM_BYTES);

    dim3 grid(N_, H_ / ROWS);  // 128 x 7
    conv1x3_roll_kernel<<<grid, THREADS, SMEM_BYTES>>>(x, w, out);
}

// round 5
// speedup vs baseline: 1.7669x; 1.0656x over previous
#include <cuda_runtime.h>
#include <cstdint>

#define N_   128
#define C_   128
#define H_   56
#define W_   56
#define O_   32
#define KW_  3

#define ROWS    8     // output h rows per block
#define C_CH    32    // channels staged per chunk
#define NCHUNK  (C_ / C_CH)   // 4
#define THREADS 448   // 8 rows * 56 units (7 w-groups * 8 o-groups)

#define SW_ELEMS   (C_ * KW_ * O_)          // 12288 floats, layout [c][k][o]
#define SX_STRIDE_R 64                      // padded row: data at idx 4..59, zeros at 3 & 60
#define SX_STRIDE_C (ROWS * SX_STRIDE_R)    // 512
#define SX_ELEMS   (C_CH * SX_STRIDE_C)     // 16384 floats per buffer
#define SMEM_BYTES ((SW_ELEMS + 2 * SX_ELEMS) * 4)   // 180224 B

extern __shared__ float smem_f[];

typedef unsigned long long ull;

__device__ __forceinline__ ull fma2(ull a, ull b, ull c) {
    ull d;
    asm("fma.rn.f32x2 %0, %1, %2, %3;" : "=l"(d) : "l"(a), "l"(b), "l"(c));
    return d;
}

__device__ __forceinline__ ull pack2(float x) {
    ull d;
    unsigned int u = __float_as_uint(x);
    asm("mov.b64 %0, {%1, %1};" : "=l"(d) : "r"(u));
    return d;
}

__device__ __forceinline__ float lo32(ull v) { return __uint_as_float((unsigned int)v); }
__device__ __forceinline__ float hi32(ull v) { return __uint_as_float((unsigned int)(v >> 32)); }

__device__ __forceinline__ void cp_async16(float* smem_dst, const float* gmem_src) {
    unsigned int d = (unsigned int)__cvta_generic_to_shared(smem_dst);
    asm volatile("cp.async.cg.shared.global [%0], [%1], 16;\n" :: "r"(d), "l"(gmem_src));
}
__device__ __forceinline__ void cp_commit() {
    asm volatile("cp.async.commit_group;\n");
}
__device__ __forceinline__ void cp_wait0() {
    asm volatile("cp.async.wait_group 0;\n");
}

__global__ void __launch_bounds__(THREADS, 1)
conv1x3_roll_kernel(const float* __restrict__ x,
                    const float* __restrict__ wgt,
                    float* __restrict__ out) {
    float* sw = smem_f;                   // [c][k][o] : 128*3*32
    float* sx0 = smem_f + SW_ELEMS;       // double buffers
    float* sx1 = sx0 + SX_ELEMS;

    const int n      = blockIdx.x;
    const int h_base = blockIdx.y * ROWS;
    const int tid    = threadIdx.x;

    const int r   = tid / 56;       // 0..7 output row within tile
    const int u   = tid % 56;
    const int w_g = u >> 3;         // 0..6  -> w0 = 8*w_g
    const int o_g = u & 7;          // 0..7  -> o0 = 4*o_g
    const int w0  = w_g * 8;
    const int o0  = o_g * 4;
    const int h   = h_base + r;

    // ---- stage all weights once: sw[c][k][o] = wgt[o][c][k] ----
    for (int idx = tid; idx < SW_ELEMS; idx += THREADS) {
        int o = idx & 31;
        int k = (idx >> 5) % 3;
        int c = idx / 96;
        sw[idx] = wgt[(o * C_ + c) * KW_ + k];
    }
    // ---- zero pads (idx 3 & 60 of every row, both buffers) once ----
    for (int q = tid; q < 2 * C_CH * ROWS; q += THREADS) {
        int rr  = q % ROWS;
        int c   = (q / ROWS) % C_CH;
        float* buf = (q < C_CH * ROWS) ? sx0 : sx1;
        float* row = buf + c * SX_STRIDE_C + rr * SX_STRIDE_R;
        row[3]  = 0.0f;
        row[60] = 0.0f;
    }

    // ---- staging lambda: chunk cc -> buffer buf ----
    auto stage = [&](float* buf, int c0) {
        // 32c * 8r * 14 float4 = 3584 loads; 448 threads -> 8 each
#pragma unroll
        for (int it = 0; it < (C_CH * ROWS * 14) / THREADS; ++it) {
            int q  = tid + it * THREADS;
            int v  = q % 14;
            int rr = (q / 14) % ROWS;
            int c  = q / (14 * ROWS);
            int hs = h_base + rr - 1;
            if (hs < 0) hs += H_;
            const float* src = x + (((size_t)n * C_ + (c0 + c)) * H_ + hs) * W_ + v * 4;
            float* dst = buf + c * SX_STRIDE_C + rr * SX_STRIDE_R + 4 + v * 4;
            cp_async16(dst, src);
        }
        cp_commit();
    };

    ull acc[2][8];
#pragma unroll
    for (int p = 0; p < 2; ++p)
#pragma unroll
        for (int i = 0; i < 8; ++i) acc[p][i] = 0ull;

    stage(sx0, 0);   // prologue

    for (int cc = 0; cc < NCHUNK; ++cc) {
        float* buf = (cc & 1) ? sx1 : sx0;
        const int c0 = cc * C_CH;

        cp_wait0();          // chunk cc data landed
        __syncthreads();     // all warps: data visible AND done computing cc-1

        if (cc + 1 < NCHUNK) {
            float* nbuf = (cc & 1) ? sx0 : sx1;   // safe: compute cc-1 done (sync above)
            stage(nbuf, c0 + C_CH);
        }

        // ---- accumulate chunk cc (overlaps with cp.async of cc+1) ----
        const float* xbase = buf + r * SX_STRIDE_R + (w0 + 3);
        const float* wbase = sw + c0 * (KW_ * O_) + o0;
        for (int c = 0; c < C_CH; ++c) {
            const float* xrow = xbase + c * SX_STRIDE_C;
            ull xd[10];
#pragma unroll
            for (int j = 0; j < 10; ++j) xd[j] = pack2(xrow[j]);

            const float* wrow = wbase + c * (KW_ * O_);
#pragma unroll
            for (int k = 0; k < 3; ++k) {
#pragma unroll
                for (int p = 0; p < 2; ++p) {
                    ull wp = *reinterpret_cast<const ull*>(wrow + k * O_ + 2 * p);
#pragma unroll
                    for (int i = 0; i < 8; ++i)
                        acc[p][i] = fma2(xd[i + k], wp, acc[p][i]);
                }
            }
        }
    }

    // ---- write out: acc[p][i] holds (o=o0+2p, o=o0+2p+1) at w = w0+i ----
#pragma unroll
    for (int p = 0; p < 2; ++p) {
        float* dst_lo = out + (((size_t)n * O_ + (o0 + 2 * p)) * H_ + h) * W_ + w0;
        float* dst_hi = dst_lo + (size_t)H_ * W_;
        float4 a, b;
        a.x = lo32(acc[p][0]); a.y = lo32(acc[p][1]); a.z = lo32(acc[p][2]); a.w = lo32(acc[p][3]);
        b.x = lo32(acc[p][4]); b.y = lo32(acc[p][5]); b.z = lo32(acc[p][6]); b.w = lo32(acc[p][7]);
        *reinterpret_cast<float4*>(dst_lo)     = a;
        *reinterpret_cast<float4*>(dst_lo + 4) = b;
        a.x = hi32(acc[p][0]); a.y = hi32(acc[p][1]); a.z = hi32(acc[p][2]); a.w = hi32(acc[p][3]);
        b.x = hi32(acc[p][4]); b.y = hi32(acc[p][5]); b.z = hi32(acc[p][6]); b.w = hi32(acc[p][7]);
        *reinterpret_cast<float4*>(dst_hi)     = a;
        *reinterpret_cast<float4*>(dst_hi + 4) = b;
    }
}

extern "C" void kernel_launch(void* const* d_in, const int* in_sizes, int n_in,
                              void* d_out, int out_size) {
    const float* x = (const float*)d_in[0];
    const float* w = (const float*)d_in[1];
    if (n_in >= 2 && in_sizes[0] == O_ * C_ * KW_) {
        const float* t = x; x = w; w = t;
    }
    float* out = (float*)d_out;

    cudaFuncSetAttribute(conv1x3_roll_kernel,
                         cudaFuncAttributeMaxDynamicSharedMemorySize, SMEM_BYTES);

    dim3 grid(N_, H_ / ROWS);  // 128 x 7
    conv1x3_roll_kernel<<<grid, THREADS, SMEM_BYTES>>>(x, w, out);
}